// round 2
// baseline (speedup 1.0000x reference)
#include <cuda_runtime.h>
#include <math.h>

#define NROWS 8192
#define D     512
#define CB    4096
#define FB    8192
#define BT    128
#define KT    8

// -------------------- scratch (device globals; no allocation) --------------------
__device__ float g_nsq_c[CB];
__device__ float g_nsq_f[FB];
__device__ float g_xnsq_c[NROWS];
__device__ float g_xnsq_f[NROWS];
__device__ unsigned long long g_best_c[NROWS];
__device__ unsigned long long g_best_f[NROWS];
__device__ float g_qc[NROWS * D];
__device__ float g_qf[NROWS * D];
__device__ float g_ci[NROWS * D];
__device__ float g_res[NROWS * D];
__device__ float g_h[NROWS * D];
__device__ float g_loss;

// -------------------- helpers --------------------
__device__ __forceinline__ unsigned long long packdi(float d, unsigned j) {
    unsigned u = __float_as_uint(d);
    // monotone map float -> unsigned (ascending); ties (equal fp32 d) -> lowest index
    u = (u & 0x80000000u) ? ~u : (u | 0x80000000u);
    return ((unsigned long long)u << 32) | (unsigned long long)j;
}

// -------------------- prep: emb sq-norms, z_coarse row sq-norms, init --------------------
__global__ void prep_kernel(const float* __restrict__ z,
                            const float* __restrict__ ce, const float* __restrict__ fe) {
    int tid = blockIdx.x * blockDim.x + threadIdx.x;
    int w = tid >> 5, lane = tid & 31;
    if (w < CB + FB + NROWS) {
        const float* src;
        if (w < CB)            src = ce + (size_t)w * D;
        else if (w < CB + FB)  src = fe + (size_t)(w - CB) * D;
        else                   src = z  + (size_t)(w - CB - FB) * 1024;  // z_coarse row
        float s = 0.f;
        #pragma unroll
        for (int it = 0; it < 4; it++) {
            float4 v = *(const float4*)(src + lane * 4 + it * 128);
            s += v.x * v.x + v.y * v.y + v.z * v.z + v.w * v.w;
        }
        #pragma unroll
        for (int o = 16; o; o >>= 1) s += __shfl_xor_sync(0xffffffffu, s, o);
        if (lane == 0) {
            if (w < CB)           g_nsq_c[w] = s;
            else if (w < CB + FB) g_nsq_f[w - CB] = s;
            else                  g_xnsq_c[w - CB - FB] = s;
        }
    }
    if (tid < NROWS) { g_best_c[tid] = ~0ull; g_best_f[tid] = ~0ull; }
    if (tid == 0) g_loss = 0.f;
}

// -------------------- tiled GEMM: MODE 0 = VQ argmin, MODE 1 = GEMM + bias --------------------
// A: [M][K] row stride lda ; B: [NB][K] row-major (K=512)
template <int MODE>
__global__ __launch_bounds__(256) void gemm128(
    const float* __restrict__ A, int lda,
    const float* __restrict__ B,
    const float* __restrict__ aux,            // MODE0: emb nsq[NB] ; MODE1: bias[512]
    const float* __restrict__ xnsq,           // MODE0: row nsq[M]
    unsigned long long* __restrict__ best,    // MODE0
    float* __restrict__ out)                  // MODE1
{
    __shared__ float As[KT][BT + 4];
    __shared__ float Bs[KT][BT + 4];
    const int t  = threadIdx.x;
    const int tx = t & 15, ty = t >> 4;
    const int row0 = blockIdx.x * BT, col0 = blockIdx.y * BT;
    const int lr = t >> 1;
    const int lk = (t & 1) * 4;

    const float* ap = A + (size_t)(row0 + lr) * lda + lk;
    const float* bp = B + (size_t)(col0 + lr) * D + lk;

    float acc[8][8];
    #pragma unroll
    for (int i = 0; i < 8; i++)
        #pragma unroll
        for (int j = 0; j < 8; j++) acc[i][j] = 0.f;

    for (int k0 = 0; k0 < D; k0 += KT) {
        float4 av = *(const float4*)(ap + k0);
        float4 bv = *(const float4*)(bp + k0);
        __syncthreads();
        As[lk + 0][lr] = av.x; As[lk + 1][lr] = av.y;
        As[lk + 2][lr] = av.z; As[lk + 3][lr] = av.w;
        Bs[lk + 0][lr] = bv.x; Bs[lk + 1][lr] = bv.y;
        Bs[lk + 2][lr] = bv.z; Bs[lk + 3][lr] = bv.w;
        __syncthreads();
        #pragma unroll
        for (int kk = 0; kk < KT; kk++) {
            float a[8], b[8];
            *(float4*)&a[0] = *(const float4*)&As[kk][ty * 8];
            *(float4*)&a[4] = *(const float4*)&As[kk][ty * 8 + 4];
            *(float4*)&b[0] = *(const float4*)&Bs[kk][tx * 8];
            *(float4*)&b[4] = *(const float4*)&Bs[kk][tx * 8 + 4];
            #pragma unroll
            for (int i = 0; i < 8; i++)
                #pragma unroll
                for (int j = 0; j < 8; j++) acc[i][j] += a[i] * b[j];
        }
    }

    if (MODE == 0) {
        __shared__ unsigned long long sbest[BT];
        if (t < BT) sbest[t] = ~0ull;
        // per-row ||x||^2 (match reference: d = fl(fl(xx+ee) - 2*dot))
        float xr[8];
        #pragma unroll
        for (int i = 0; i < 8; i++) xr[i] = xnsq[row0 + ty * 8 + i];
        __syncthreads();
        #pragma unroll
        for (int i = 0; i < 8; i++) {
            unsigned long long m = ~0ull;
            #pragma unroll
            for (int j = 0; j < 8; j++) {
                int col = col0 + tx * 8 + j;
                float t1 = __fadd_rn(xr[i], aux[col]);
                float d  = __fadd_rn(t1, -2.f * acc[i][j]);
                unsigned long long p = packdi(d, (unsigned)col);
                if (p < m) m = p;
            }
            atomicMin(&sbest[ty * 8 + i], m);
        }
        __syncthreads();
        if (t < BT) atomicMin(&best[row0 + t], sbest[t]);
    } else {
        #pragma unroll
        for (int i = 0; i < 8; i++) {
            int r = row0 + ty * 8 + i;
            #pragma unroll
            for (int j = 0; j < 8; j++) {
                int c = col0 + tx * 8 + j;
                out[(size_t)r * D + c] = acc[i][j] + aux[c];
            }
        }
    }
}

// -------------------- gather q = emb[idx], accumulate sum((q-x)^2) --------------------
__global__ void gather_loss(const float* __restrict__ emb,
                            const unsigned long long* __restrict__ best,
                            const float* __restrict__ x, int ldx,
                            float* __restrict__ q)
{
    int r = blockIdx.x;
    int j = (int)(best[r] & 0xffffffffu);
    const float* e  = emb + (size_t)j * D;
    const float* xr = x + (size_t)r * ldx;
    float* qr = q + (size_t)r * D;
    float ls = 0.f;
    for (int k = threadIdx.x; k < D; k += blockDim.x) {
        float ev = e[k];
        qr[k] = ev;
        float dd = ev - xr[k];
        ls += dd * dd;
    }
    #pragma unroll
    for (int o = 16; o; o >>= 1) ls += __shfl_xor_sync(0xffffffffu, ls, o);
    __shared__ float ws[8];
    int w = threadIdx.x >> 5;
    if ((threadIdx.x & 31) == 0) ws[w] = ls;
    __syncthreads();
    if (threadIdx.x == 0) {
        float s = 0.f;
        for (int i = 0; i < 8; i++) s += ws[i];
        atomicAdd(&g_loss, s);
    }
}

// -------------------- LayerNorm + leakyReLU + fused follow-up --------------------
// MODE 0 (c2f): ci = act ; res = z_fine - gc*act ; g_xnsq_f[r] = sum(res^2)
// MODE 1 (f2c): out[:, :512] = qc + 0.1*gf*act ; out[:, 512:] = qf + gc*ci ; write loss
template <int MODE>
__global__ void ln_kernel(const float* __restrict__ h,
                          const float* __restrict__ g, const float* __restrict__ be,
                          const float* __restrict__ z,
                          const float* __restrict__ gc_raw, const float* __restrict__ gf_raw,
                          float* __restrict__ out)
{
    int r = blockIdx.x;
    int j = threadIdx.x;  // 512 threads
    float hv = h[(size_t)r * D + j];

    float s = hv, sq = hv * hv;
    #pragma unroll
    for (int o = 16; o; o >>= 1) {
        s  += __shfl_xor_sync(0xffffffffu, s, o);
        sq += __shfl_xor_sync(0xffffffffu, sq, o);
    }
    __shared__ float s1[16], s2[16];
    int w = j >> 5, lane = j & 31;
    if (lane == 0) { s1[w] = s; s2[w] = sq; }
    __syncthreads();
    if (w == 0) {
        s  = (lane < 16) ? s1[lane] : 0.f;
        sq = (lane < 16) ? s2[lane] : 0.f;
        #pragma unroll
        for (int o = 8; o; o >>= 1) {
            s  += __shfl_xor_sync(0xffffffffu, s, o);
            sq += __shfl_xor_sync(0xffffffffu, sq, o);
        }
        if (lane == 0) { s1[0] = s; s2[0] = sq; }
    }
    __syncthreads();
    float mean = s1[0] * (1.f / D);
    float var  = s2[0] * (1.f / D) - mean * mean;
    float y = (hv - mean) * rsqrtf(var + 1e-5f) * g[j] + be[j];
    float act = y > 0.f ? y : 0.1f * y;
    float gcv = 1.f / (1.f + expf(-gc_raw[0]));

    if (MODE == 0) {
        float rv = z[(size_t)r * 1024 + D + j] - gcv * act;
        g_ci[(size_t)r * D + j]  = act;
        g_res[(size_t)r * D + j] = rv;
        // reduce sum(res^2) for the fine-stage distance formula
        float rq = rv * rv;
        #pragma unroll
        for (int o = 16; o; o >>= 1) rq += __shfl_xor_sync(0xffffffffu, rq, o);
        __syncthreads();
        if (lane == 0) s1[w] = rq;
        __syncthreads();
        if (j == 0) {
            float tt = 0.f;
            #pragma unroll
            for (int i = 0; i < 16; i++) tt += s1[i];
            g_xnsq_f[r] = tt;
        }
    } else {
        float gfv = 1.f / (1.f + expf(-gf_raw[0]));
        out[(size_t)r * 1024 + j]     = g_qc[(size_t)r * D + j] + 0.1f * gfv * act;
        out[(size_t)r * 1024 + D + j] = g_qf[(size_t)r * D + j] + gcv * g_ci[(size_t)r * D + j];
        if (r == 0 && j == 0)
            out[(size_t)NROWS * 1024] = 1.25f * g_loss / (float)((size_t)NROWS * D);
    }
}

// -------------------- launch --------------------
extern "C" void kernel_launch(void* const* d_in, const int* in_sizes, int n_in,
                              void* d_out, int out_size) {
    const float* z      = (const float*)d_in[0];
    const float* ce     = (const float*)d_in[1];
    const float* fe     = (const float*)d_in[2];
    const float* w_c2f  = (const float*)d_in[3];
    const float* b_c2f  = (const float*)d_in[4];
    const float* g_c2f  = (const float*)d_in[5];
    const float* be_c2f = (const float*)d_in[6];
    const float* w_f2c  = (const float*)d_in[7];
    const float* b_f2c  = (const float*)d_in[8];
    const float* g_f2c  = (const float*)d_in[9];
    const float* be_f2c = (const float*)d_in[10];
    const float* gc_raw = (const float*)d_in[11];
    const float* gf_raw = (const float*)d_in[12];
    float* out = (float*)d_out;

    float *nsq_c, *nsq_f, *xnsq_c, *xnsq_f, *qc, *qf, *res, *h;
    unsigned long long *best_c, *best_f;
    cudaGetSymbolAddress((void**)&nsq_c, g_nsq_c);
    cudaGetSymbolAddress((void**)&nsq_f, g_nsq_f);
    cudaGetSymbolAddress((void**)&xnsq_c, g_xnsq_c);
    cudaGetSymbolAddress((void**)&xnsq_f, g_xnsq_f);
    cudaGetSymbolAddress((void**)&best_c, g_best_c);
    cudaGetSymbolAddress((void**)&best_f, g_best_f);
    cudaGetSymbolAddress((void**)&qc, g_qc);
    cudaGetSymbolAddress((void**)&qf, g_qf);
    cudaGetSymbolAddress((void**)&res, g_res);
    cudaGetSymbolAddress((void**)&h, g_h);

    // 1) norms + init
    prep_kernel<<<(CB + FB + NROWS) * 32 / 256, 256>>>(z, ce, fe);
    // 2) coarse VQ argmin: z_coarse (lda=1024) vs coarse_emb
    gemm128<0><<<dim3(NROWS / BT, CB / BT), 256>>>(z, 1024, ce, nsq_c, xnsq_c, best_c, nullptr);
    // 3) gather q_c + coarse loss
    gather_loss<<<NROWS, 256>>>(ce, best_c, z, 1024, qc);
    // 4) h = q_c @ w_c2f^T + b
    gemm128<1><<<dim3(NROWS / BT, D / BT), 256>>>(qc, D, w_c2f, b_c2f, nullptr, nullptr, h);
    // 5) LN + lrelu -> ci ; res = z_fine - gc*ci ; row norms of res
    ln_kernel<0><<<NROWS, 512>>>(h, g_c2f, be_c2f, z, gc_raw, gf_raw, nullptr);
    // 6) fine VQ argmin: res vs fine_emb
    gemm128<0><<<dim3(NROWS / BT, FB / BT), 256>>>(res, D, fe, nsq_f, xnsq_f, best_f, nullptr);
    // 7) gather q_f + fine loss
    gather_loss<<<NROWS, 256>>>(fe, best_f, res, D, qf);
    // 8) h = q_f @ w_f2c^T + b
    gemm128<1><<<dim3(NROWS / BT, D / BT), 256>>>(qf, D, w_f2c, b_f2c, nullptr, nullptr, h);
    // 9) LN + lrelu -> assemble output + loss scalar
    ln_kernel<1><<<NROWS, 512>>>(h, g_f2c, be_f2c, z, gc_raw, gf_raw, out);
}

// round 3
// speedup vs baseline: 1.0218x; 1.0218x over previous
#include <cuda_runtime.h>
#include <math.h>

#define NROWS 8192
#define D     512
#define CB    4096
#define FB    8192
#define BT    128
#define KT    8
#define NIT   (D / KT)

typedef unsigned long long ull;

// -------------------- scratch (device globals; no allocation) --------------------
__device__ float g_nsq_c[CB];
__device__ float g_nsq_f[FB];
__device__ float g_xnsq_c[NROWS];
__device__ float g_xnsq_f[NROWS];
__device__ ull g_best_c[NROWS];
__device__ ull g_best_f[NROWS];
__device__ float g_qc[NROWS * D];
__device__ float g_qf[NROWS * D];
__device__ float g_ci[NROWS * D];
__device__ float g_res[NROWS * D];
__device__ float g_h[NROWS * D];
__device__ float g_loss;

// -------------------- packed f32x2 helpers --------------------
__device__ __forceinline__ ull pack2(float lo, float hi) {
    ull r;
    asm("mov.b64 %0, {%1, %2};" : "=l"(r) : "f"(lo), "f"(hi));
    return r;
}
__device__ __forceinline__ void unpack2(ull v, float& lo, float& hi) {
    asm("mov.b64 {%0, %1}, %2;" : "=f"(lo), "=f"(hi) : "l"(v));
}
__device__ __forceinline__ void ffma2(ull& acc, ull a, ull b) {
    asm("fma.rn.f32x2 %0, %1, %2, %0;" : "+l"(acc) : "l"(a), "l"(b));
}

__device__ __forceinline__ ull packdi(float d, unsigned j) {
    unsigned u = __float_as_uint(d);
    u = (u & 0x80000000u) ? ~u : (u | 0x80000000u);
    return ((ull)u << 32) | (ull)j;
}

// -------------------- prep: emb sq-norms, z_coarse row sq-norms, init --------------------
__global__ void prep_kernel(const float* __restrict__ z,
                            const float* __restrict__ ce, const float* __restrict__ fe) {
    int tid = blockIdx.x * blockDim.x + threadIdx.x;
    int w = tid >> 5, lane = tid & 31;
    if (w < CB + FB + NROWS) {
        const float* src;
        if (w < CB)            src = ce + (size_t)w * D;
        else if (w < CB + FB)  src = fe + (size_t)(w - CB) * D;
        else                   src = z  + (size_t)(w - CB - FB) * 1024;  // z_coarse row
        float s = 0.f;
        #pragma unroll
        for (int it = 0; it < 4; it++) {
            float4 v = *(const float4*)(src + lane * 4 + it * 128);
            s += v.x * v.x + v.y * v.y + v.z * v.z + v.w * v.w;
        }
        #pragma unroll
        for (int o = 16; o; o >>= 1) s += __shfl_xor_sync(0xffffffffu, s, o);
        if (lane == 0) {
            if (w < CB)           g_nsq_c[w] = s;
            else if (w < CB + FB) g_nsq_f[w - CB] = s;
            else                  g_xnsq_c[w - CB - FB] = s;
        }
    }
    if (tid < NROWS) { g_best_c[tid] = ~0ull; g_best_f[tid] = ~0ull; }
    if (tid == 0) g_loss = 0.f;
}

// -------------------- tiled GEMM (FFMA2, double-buffered) --------------------
// MODE 0 = VQ argmin epilogue, MODE 1 = GEMM + bias
// A: [M][K] row stride lda ; B: [NB][K] row-major (K=512)
template <int MODE>
__global__ __launch_bounds__(256) void gemm128(
    const float* __restrict__ A, int lda,
    const float* __restrict__ B,
    const float* __restrict__ aux,            // MODE0: emb nsq[NB] ; MODE1: bias[512]
    const float* __restrict__ xnsq,           // MODE0: row nsq[M]
    ull* __restrict__ best,                   // MODE0
    float* __restrict__ out)                  // MODE1
{
    __shared__ float As[2][KT][BT + 4];
    __shared__ float Bs[2][KT][BT + 4];
    const int t  = threadIdx.x;
    const int tx = t & 15, ty = t >> 4;
    const int row0 = blockIdx.x * BT, col0 = blockIdx.y * BT;
    const int lr = t >> 1;
    const int lk = (t & 1) * 4;

    const float* ap = A + (size_t)(row0 + lr) * lda + lk;
    const float* bp = B + (size_t)(col0 + lr) * D + lk;

    ull acc[8][4];
    #pragma unroll
    for (int i = 0; i < 8; i++)
        #pragma unroll
        for (int j = 0; j < 4; j++) acc[i][j] = 0ull;

    // prologue: tile 0 -> buffer 0
    float4 av = *(const float4*)(ap);
    float4 bv = *(const float4*)(bp);
    As[0][lk + 0][lr] = av.x; As[0][lk + 1][lr] = av.y;
    As[0][lk + 2][lr] = av.z; As[0][lk + 3][lr] = av.w;
    Bs[0][lk + 0][lr] = bv.x; Bs[0][lk + 1][lr] = bv.y;
    Bs[0][lk + 2][lr] = bv.z; Bs[0][lk + 3][lr] = bv.w;
    __syncthreads();

    int buf = 0;
    #pragma unroll 1
    for (int it = 0; it < NIT; ++it) {
        const bool has_next = (it + 1 < NIT);
        if (has_next) {
            av = *(const float4*)(ap + (it + 1) * KT);
            bv = *(const float4*)(bp + (it + 1) * KT);
        }
        #pragma unroll
        for (int kk = 0; kk < KT; kk++) {
            float a[8], b[8];
            *(float4*)&a[0] = *(const float4*)&As[buf][kk][ty * 8];
            *(float4*)&a[4] = *(const float4*)&As[buf][kk][ty * 8 + 4];
            *(float4*)&b[0] = *(const float4*)&Bs[buf][kk][tx * 8];
            *(float4*)&b[4] = *(const float4*)&Bs[buf][kk][tx * 8 + 4];
            ull a2[8], b2[4];
            #pragma unroll
            for (int i = 0; i < 8; i++) a2[i] = pack2(a[i], a[i]);
            #pragma unroll
            for (int j = 0; j < 4; j++) b2[j] = pack2(b[2 * j], b[2 * j + 1]);
            #pragma unroll
            for (int i = 0; i < 8; i++)
                #pragma unroll
                for (int j = 0; j < 4; j++) ffma2(acc[i][j], a2[i], b2[j]);
        }
        if (has_next) {
            int nb = buf ^ 1;
            As[nb][lk + 0][lr] = av.x; As[nb][lk + 1][lr] = av.y;
            As[nb][lk + 2][lr] = av.z; As[nb][lk + 3][lr] = av.w;
            Bs[nb][lk + 0][lr] = bv.x; Bs[nb][lk + 1][lr] = bv.y;
            Bs[nb][lk + 2][lr] = bv.z; Bs[nb][lk + 3][lr] = bv.w;
            __syncthreads();
            buf = nb;
        }
    }

    if (MODE == 0) {
        __shared__ ull sbest[BT];
        if (t < BT) sbest[t] = ~0ull;
        float xr[8];
        #pragma unroll
        for (int i = 0; i < 8; i++) xr[i] = xnsq[row0 + ty * 8 + i];
        __syncthreads();
        #pragma unroll
        for (int i = 0; i < 8; i++) {
            ull m = ~0ull;
            #pragma unroll
            for (int j = 0; j < 4; j++) {
                float d0, d1;
                unpack2(acc[i][j], d0, d1);
                int col = col0 + tx * 8 + 2 * j;
                // match reference rounding: d = fl(fl(xx + ee) - 2*dot)
                float ta = __fadd_rn(xr[i], aux[col]);
                float tb = __fadd_rn(xr[i], aux[col + 1]);
                float da = __fadd_rn(ta, -2.f * d0);
                float db = __fadd_rn(tb, -2.f * d1);
                ull pa = packdi(da, (unsigned)col);
                ull pb = packdi(db, (unsigned)(col + 1));
                if (pa < m) m = pa;
                if (pb < m) m = pb;
            }
            atomicMin(&sbest[ty * 8 + i], m);
        }
        __syncthreads();
        if (t < BT) atomicMin(&best[row0 + t], sbest[t]);
    } else {
        #pragma unroll
        for (int i = 0; i < 8; i++) {
            int r = row0 + ty * 8 + i;
            #pragma unroll
            for (int j = 0; j < 4; j++) {
                float d0, d1;
                unpack2(acc[i][j], d0, d1);
                int c = col0 + tx * 8 + 2 * j;
                float2 o2 = make_float2(d0 + aux[c], d1 + aux[c + 1]);
                *(float2*)&out[(size_t)r * D + c] = o2;
            }
        }
    }
}

// -------------------- gather q = emb[idx], accumulate sum((q-x)^2) --------------------
__global__ void gather_loss(const float* __restrict__ emb,
                            const ull* __restrict__ best,
                            const float* __restrict__ x, int ldx,
                            float* __restrict__ q)
{
    int r = blockIdx.x;
    int j = (int)(best[r] & 0xffffffffu);
    const float* e  = emb + (size_t)j * D;
    const float* xr = x + (size_t)r * ldx;
    float* qr = q + (size_t)r * D;
    float ls = 0.f;
    for (int k = threadIdx.x; k < D; k += blockDim.x) {
        float ev = e[k];
        qr[k] = ev;
        float dd = ev - xr[k];
        ls += dd * dd;
    }
    #pragma unroll
    for (int o = 16; o; o >>= 1) ls += __shfl_xor_sync(0xffffffffu, ls, o);
    __shared__ float ws[8];
    int w = threadIdx.x >> 5;
    if ((threadIdx.x & 31) == 0) ws[w] = ls;
    __syncthreads();
    if (threadIdx.x == 0) {
        float s = 0.f;
        for (int i = 0; i < 8; i++) s += ws[i];
        atomicAdd(&g_loss, s);
    }
}

// -------------------- LayerNorm + leakyReLU + fused follow-up --------------------
// MODE 0 (c2f): ci = act ; res = z_fine - gc*act ; g_xnsq_f[r] = sum(res^2)
// MODE 1 (f2c): out[:, :512] = qc + 0.1*gf*act ; out[:, 512:] = qf + gc*ci ; loss
template <int MODE>
__global__ void ln_kernel(const float* __restrict__ h,
                          const float* __restrict__ g, const float* __restrict__ be,
                          const float* __restrict__ z,
                          const float* __restrict__ gc_raw, const float* __restrict__ gf_raw,
                          float* __restrict__ out)
{
    int r = blockIdx.x;
    int j = threadIdx.x;  // 512 threads
    float hv = h[(size_t)r * D + j];

    float s = hv, sq = hv * hv;
    #pragma unroll
    for (int o = 16; o; o >>= 1) {
        s  += __shfl_xor_sync(0xffffffffu, s, o);
        sq += __shfl_xor_sync(0xffffffffu, sq, o);
    }
    __shared__ float s1[16], s2[16];
    int w = j >> 5, lane = j & 31;
    if (lane == 0) { s1[w] = s; s2[w] = sq; }
    __syncthreads();
    if (w == 0) {
        s  = (lane < 16) ? s1[lane] : 0.f;
        sq = (lane < 16) ? s2[lane] : 0.f;
        #pragma unroll
        for (int o = 8; o; o >>= 1) {
            s  += __shfl_xor_sync(0xffffffffu, s, o);
            sq += __shfl_xor_sync(0xffffffffu, sq, o);
        }
        if (lane == 0) { s1[0] = s; s2[0] = sq; }
    }
    __syncthreads();
    float mean = s1[0] * (1.f / D);
    float var  = s2[0] * (1.f / D) - mean * mean;
    float y = (hv - mean) * rsqrtf(var + 1e-5f) * g[j] + be[j];
    float act = y > 0.f ? y : 0.1f * y;
    float gcv = 1.f / (1.f + expf(-gc_raw[0]));

    if (MODE == 0) {
        float rv = z[(size_t)r * 1024 + D + j] - gcv * act;
        g_ci[(size_t)r * D + j]  = act;
        g_res[(size_t)r * D + j] = rv;
        float rq = rv * rv;
        #pragma unroll
        for (int o = 16; o; o >>= 1) rq += __shfl_xor_sync(0xffffffffu, rq, o);
        __syncthreads();
        if (lane == 0) s1[w] = rq;
        __syncthreads();
        if (j == 0) {
            float tt = 0.f;
            #pragma unroll
            for (int i = 0; i < 16; i++) tt += s1[i];
            g_xnsq_f[r] = tt;
        }
    } else {
        float gfv = 1.f / (1.f + expf(-gf_raw[0]));
        out[(size_t)r * 1024 + j]     = g_qc[(size_t)r * D + j] + 0.1f * gfv * act;
        out[(size_t)r * 1024 + D + j] = g_qf[(size_t)r * D + j] + gcv * g_ci[(size_t)r * D + j];
        if (r == 0 && j == 0)
            out[(size_t)NROWS * 1024] = 1.25f * g_loss / (float)((size_t)NROWS * D);
    }
}

// -------------------- launch --------------------
extern "C" void kernel_launch(void* const* d_in, const int* in_sizes, int n_in,
                              void* d_out, int out_size) {
    const float* z      = (const float*)d_in[0];
    const float* ce     = (const float*)d_in[1];
    const float* fe     = (const float*)d_in[2];
    const float* w_c2f  = (const float*)d_in[3];
    const float* b_c2f  = (const float*)d_in[4];
    const float* g_c2f  = (const float*)d_in[5];
    const float* be_c2f = (const float*)d_in[6];
    const float* w_f2c  = (const float*)d_in[7];
    const float* b_f2c  = (const float*)d_in[8];
    const float* g_f2c  = (const float*)d_in[9];
    const float* be_f2c = (const float*)d_in[10];
    const float* gc_raw = (const float*)d_in[11];
    const float* gf_raw = (const float*)d_in[12];
    float* out = (float*)d_out;

    float *nsq_c, *nsq_f, *xnsq_c, *xnsq_f, *qc, *qf, *res, *h;
    ull *best_c, *best_f;
    cudaGetSymbolAddress((void**)&nsq_c, g_nsq_c);
    cudaGetSymbolAddress((void**)&nsq_f, g_nsq_f);
    cudaGetSymbolAddress((void**)&xnsq_c, g_xnsq_c);
    cudaGetSymbolAddress((void**)&xnsq_f, g_xnsq_f);
    cudaGetSymbolAddress((void**)&best_c, g_best_c);
    cudaGetSymbolAddress((void**)&best_f, g_best_f);
    cudaGetSymbolAddress((void**)&qc, g_qc);
    cudaGetSymbolAddress((void**)&qf, g_qf);
    cudaGetSymbolAddress((void**)&res, g_res);
    cudaGetSymbolAddress((void**)&h, g_h);

    // 1) norms + init
    prep_kernel<<<(CB + FB + NROWS) * 32 / 256, 256>>>(z, ce, fe);
    // 2) coarse VQ argmin: z_coarse (lda=1024) vs coarse_emb
    gemm128<0><<<dim3(NROWS / BT, CB / BT), 256>>>(z, 1024, ce, nsq_c, xnsq_c, best_c, nullptr);
    // 3) gather q_c + coarse loss
    gather_loss<<<NROWS, 256>>>(ce, best_c, z, 1024, qc);
    // 4) h = q_c @ w_c2f^T + b
    gemm128<1><<<dim3(NROWS / BT, D / BT), 256>>>(qc, D, w_c2f, b_c2f, nullptr, nullptr, h);
    // 5) LN + lrelu -> ci ; res = z_fine - gc*ci ; row norms of res
    ln_kernel<0><<<NROWS, 512>>>(h, g_c2f, be_c2f, z, gc_raw, gf_raw, nullptr);
    // 6) fine VQ argmin: res vs fine_emb
    gemm128<0><<<dim3(NROWS / BT, FB / BT), 256>>>(res, D, fe, nsq_f, xnsq_f, best_f, nullptr);
    // 7) gather q_f + fine loss
    gather_loss<<<NROWS, 256>>>(fe, best_f, res, D, qf);
    // 8) h = q_f @ w_f2c^T + b
    gemm128<1><<<dim3(NROWS / BT, D / BT), 256>>>(qf, D, w_f2c, b_f2c, nullptr, nullptr, h);
    // 9) LN + lrelu -> assemble output + loss scalar
    ln_kernel<1><<<NROWS, 512>>>(h, g_f2c, be_f2c, z, gc_raw, gf_raw, out);
}